// round 9
// baseline (speedup 1.0000x reference)
#include <cuda_runtime.h>

#define NTHREADS 512
#define SAMPLES  32
#define HDIM     50
#define G4       256           // 64 units * 4 gates, cols 4j+g
#define TSTEPS   256
#define HROW     36            // h row [k][s0..s31] + 4 pad
#define HBUF     (50*HROW)
#define XROW     36
#define XBUF     (32*XROW)

typedef unsigned long long ull;

__device__ __forceinline__ ull pack2(float lo, float hi) {
    ull r; asm("mov.b64 %0, {%1,%2};" : "=l"(r) : "f"(lo), "f"(hi)); return r;
}
__device__ __forceinline__ void unpack2(ull v, float& lo, float& hi) {
    asm("mov.b64 {%0,%1}, %2;" : "=f"(lo), "=f"(hi) : "l"(v));
}
__device__ __forceinline__ ull fma2(ull a, ull b, ull c) {
    ull d; asm("fma.rn.f32x2 %0, %1, %2, %3;" : "=l"(d) : "l"(a), "l"(b), "l"(c)); return d;
}
__device__ __forceinline__ ull add2(ull a, ull b) {
    ull d; asm("add.rn.f32x2 %0, %1, %2;" : "=l"(d) : "l"(a), "l"(b)); return d;
}
__device__ __forceinline__ float sigmoidf_(float x) {
    return __fdividef(1.f, 1.f + __expf(-x));
}
__device__ __forceinline__ float tanhf_(float x) {
    return fmaf(2.f, sigmoidf_(2.f * x), -1.f);
}

// Dynamic shared layout (floats):
//  Ws   [51*256]  : rows 0..49 = W_hh (col 4j+g), row 50 = W_ih; zeros j>=50
//  bbv  [256]     : b_ih + b_hh
//  hb   [2*50*36] : double-buffered h, rows [k][s]
//  xs   [2*32*36] : double-buffered x tiles [tt][s]
//  part [2*8*256] ull : k-split partial accumulators (2 regions)
#define OFF_WS   0
#define OFF_BB   (51*G4)                    // 13056
#define OFF_HB   (OFF_BB + G4)              // 13312
#define OFF_XS   (OFF_HB + 2*HBUF)          // 16912
#define OFF_PART (OFF_XS + 2*XBUF)          // 19216 (even -> 8B aligned)
#define SMEM_FLOATS (OFF_PART + 2*8*256*2)  // + 8192 floats = 27408

__global__ void __launch_bounds__(NTHREADS, 1) lstm_q_kernel(
    const float* __restrict__ x,    const float* __restrict__ W_ih,
    const float* __restrict__ W_hh, const float* __restrict__ b_ih,
    const float* __restrict__ b_hh, const float* __restrict__ Wp,
    const float* __restrict__ bp,   const float* __restrict__ qw,
    const float* __restrict__ Wo,   const float* __restrict__ bo,
    float* __restrict__ out)
{
    extern __shared__ float sm[];
    float* Ws  = sm + OFF_WS;
    float* bbv = sm + OFF_BB;
    float* hb  = sm + OFF_HB;
    float* xs  = sm + OFF_XS;
    ull*   prt = (ull*)(sm + OFF_PART);

    const int tid   = threadIdx.x;
    const int lane  = tid & 31;
    const int warp  = tid >> 5;
    const int kg    = warp >> 3;           // k-half (0: k 0..24, 1: k 25..49 + x)
    const int ug    = warp & 1;            // unit group
    const int sg    = (warp >> 1) & 3;     // sample group (8 samples)
    const int j     = 32 * ug + lane;      // this thread's hidden unit
    const int sb    = 8 * sg;
    const int tix   = tid & 255;           // partner-matched index across kg halves
    const int bbase = blockIdx.x * SAMPLES;

    // ---- stage weights ----
    for (int idx = tid; idx < 51 * G4; idx += NTHREADS) {
        int k = idx >> 8, c = idx & 255;
        int jj = c >> 2, g = c & 3;
        float v = 0.f;
        if (jj < HDIM) {
            if (k < HDIM)      v = W_hh[(g * HDIM + jj) * HDIM + k];
            else               v = W_ih[g * HDIM + jj];
        }
        Ws[idx] = v;
    }
    for (int idx = tid; idx < G4; idx += NTHREADS) {
        int jj = idx >> 2, g = idx & 3;
        bbv[idx] = (jj < HDIM) ? (b_ih[g * HDIM + jj] + b_hh[g * HDIM + jj]) : 0.f;
    }
    for (int idx = tid; idx < 2 * HBUF; idx += NTHREADS) hb[idx] = 0.f;
    for (int idx = tid; idx < 32 * 32; idx += NTHREADS) {
        int ss = idx >> 5, tt = idx & 31;
        xs[tt * XROW + ss] = x[(bbase + ss) * TSTEPS + tt];
    }
    __syncthreads();

    // persistent dup'd constants
    float4 b4  = *(const float4*)(bbv + 4 * j);
    ull bb[4]  = { pack2(b4.x, b4.x), pack2(b4.y, b4.y),
                   pack2(b4.z, b4.z), pack2(b4.w, b4.w) };
    float4 xw4 = *(const float4*)(Ws + 50 * G4 + 4 * j);
    ull xw[4]  = { pack2(xw4.x, xw4.x), pack2(xw4.y, xw4.y),
                   pack2(xw4.z, xw4.z), pack2(xw4.w, xw4.w) };

    float c_st[4];                          // finalized: 4 samples per thread
    #pragma unroll
    for (int i = 0; i < 4; i++) c_st[i] = 0.f;

    const int k0 = kg * 25;
    const int pf = kg ? 2 : 0;              // finalized pair indices pf, pf+1
    const int pb = kg ? 0 : 2;              // exported pair indices pb, pb+1
    ull* myreg = prt + kg * 2048;           // this half's export region
    ull* otreg = prt + (kg ^ 1) * 2048;     // partner's export region

    int buf = 0;

    for (int t = 0; t < TSTEPS; t++) {
        __syncthreads();               // h of prev step + part reads done

        if ((t & 31) == 0 && t + 32 < TSTEPS) {
            float* xd = xs + (((t >> 5) & 1) ^ 1) * XBUF;
            for (int idx = tid; idx < 32 * 32; idx += NTHREADS) {
                int ss = idx >> 5, tt = idx & 31;
                xd[tt * XROW + ss] = x[(bbase + ss) * TSTEPS + t + 32 + tt];
            }
        }

        const float* hB = hb + buf * HBUF;

        ull acc[4][4];                 // [gate][sample pair], bias added by kg=0 only
        #pragma unroll
        for (int g = 0; g < 4; g++)
            #pragma unroll
            for (int p = 0; p < 4; p++) acc[g][p] = kg ? 0ull : bb[g];

        #pragma unroll
        for (int kk = 0; kk < 25; kk++) {
            const int k = k0 + kk;
            float4 w4 = *(const float4*)(Ws + k * G4 + 4 * j);   // dense LDS.128
            ull wd[4] = { pack2(w4.x, w4.x), pack2(w4.y, w4.y),
                          pack2(w4.z, w4.z), pack2(w4.w, w4.w) };
            const float* hr = hB + k * HROW + sb;
            ull hp[4] = { *(const ull*)(hr + 0), *(const ull*)(hr + 2),
                          *(const ull*)(hr + 4), *(const ull*)(hr + 6) };
            #pragma unroll
            for (int g = 0; g < 4; g++)
                #pragma unroll
                for (int p = 0; p < 4; p++)
                    acc[g][p] = fma2(hp[p], wd[g], acc[g][p]);
        }
        if (kg) {  // x contribution
            const float* xrow = xs + ((t >> 5) & 1) * XBUF + (t & 31) * XROW + sb;
            ull xp[4] = { *(const ull*)(xrow + 0), *(const ull*)(xrow + 2),
                          *(const ull*)(xrow + 4), *(const ull*)(xrow + 6) };
            #pragma unroll
            for (int g = 0; g < 4; g++)
                #pragma unroll
                for (int p = 0; p < 4; p++)
                    acc[g][p] = fma2(xp[p], xw[g], acc[g][p]);
        }

        // export non-finalized pairs
        #pragma unroll
        for (int g = 0; g < 4; g++)
            #pragma unroll
            for (int q = 0; q < 2; q++)
                myreg[(g * 2 + q) * 256 + tix] = acc[g][pb + q];
        __syncthreads();
        // import partner's partials into finalized pairs
        #pragma unroll
        for (int g = 0; g < 4; g++)
            #pragma unroll
            for (int q = 0; q < 2; q++)
                acc[g][pf + q] = add2(acc[g][pf + q], otreg[(g * 2 + q) * 256 + tix]);

        // ---- gates for finalized samples ----
        float hv[4];
        #pragma unroll
        for (int q = 0; q < 2; q++) {
            const int p = pf + q;
            float zi0, zi1, zf0, zf1, zg0, zg1, zo0, zo1;
            unpack2(acc[0][p], zi0, zi1);
            unpack2(acc[1][p], zf0, zf1);
            unpack2(acc[2][p], zg0, zg1);
            unpack2(acc[3][p], zo0, zo1);
            float i0 = sigmoidf_(zi0), i1 = sigmoidf_(zi1);
            float f0 = sigmoidf_(zf0), f1 = sigmoidf_(zf1);
            float g0 = tanhf_(zg0),    g1 = tanhf_(zg1);
            float o0 = sigmoidf_(zo0), o1 = sigmoidf_(zo1);
            float cA = fmaf(f0, c_st[2*q],   i0 * g0);
            float cB = fmaf(f1, c_st[2*q+1], i1 * g1);
            c_st[2*q]   = cA;
            c_st[2*q+1] = cB;
            hv[2*q]   = o0 * tanhf_(cA);
            hv[2*q+1] = o1 * tanhf_(cB);
        }
        if (j < HDIM) {
            float* hn = hb + (buf ^ 1) * HBUF + j * HROW + sb + 4 * kg;
            *(float4*)hn = make_float4(hv[0], hv[1], hv[2], hv[3]);
        }
        buf ^= 1;
    }

    __syncthreads();   // final h visible

    // ---------------- quantum head: 1 thread per sample ----------------
    if (tid < SAMPLES) {
        const float* hfin = hb + buf * HBUF + tid;

        float ang[4];
        #pragma unroll
        for (int w = 0; w < 4; w++) {
            float a = bp[w];
            for (int k = 0; k < HDIM; k++) a = fmaf(Wp[w * HDIM + k], hfin[k * HROW], a);
            ang[w] = tanhf_(a) * 1.5707963267948966f;
        }

        float re[16], im[16];
        #pragma unroll
        for (int i = 0; i < 16; i++) { re[i] = 0.f; im[i] = 0.f; }
        re[0] = 1.f;

        #pragma unroll
        for (int w = 0; w < 4; w++) {
            float sw, cw;
            sincosf(0.5f * ang[w], &sw, &cw);
            const int m = 8 >> w;
            #pragma unroll
            for (int i0 = 0; i0 < 16; i0++) {
                if (!(i0 & m)) {
                    int i1 = i0 | m;
                    float r0 = re[i0], q0 = im[i0], r1 = re[i1], q1 = im[i1];
                    re[i0] = cw * r0 + sw * q1;  im[i0] = cw * q0 - sw * r1;
                    re[i1] = cw * r1 + sw * q0;  im[i1] = cw * q1 - sw * r0;
                }
            }
        }

        #pragma unroll
        for (int l = 0; l < 2; l++) {
            #pragma unroll
            for (int w = 0; w < 4; w++) {
                const float* q = qw + (l * 4 + w) * 3;
                float phi = q[0], th = q[1], om = q[2];
                float st_, ct_; sincosf(0.5f * th, &st_, &ct_);
                float sa, ca;   sincosf(0.5f * (phi + om), &sa, &ca);
                float sb2, cb2; sincosf(0.5f * (phi - om), &sb2, &cb2);
                float u00r =  ct_ * ca,  u00i = -ct_ * sa;
                float u01r = -st_ * cb2, u01i = -st_ * sb2;
                float u10r =  st_ * cb2, u10i = -st_ * sb2;
                float u11r =  ct_ * ca,  u11i =  ct_ * sa;
                const int m = 8 >> w;
                #pragma unroll
                for (int i0 = 0; i0 < 16; i0++) {
                    if (!(i0 & m)) {
                        int i1 = i0 | m;
                        float r0 = re[i0], q0 = im[i0], r1 = re[i1], q1 = im[i1];
                        re[i0] = u00r*r0 - u00i*q0 + u01r*r1 - u01i*q1;
                        im[i0] = u00r*q0 + u00i*r0 + u01r*q1 + u01i*r1;
                        re[i1] = u10r*r0 - u10i*q0 + u11r*r1 - u11i*q1;
                        im[i1] = u10r*q0 + u10i*r0 + u11r*q1 + u11i*r1;
                    }
                }
            }
            const int r = (l % 3) + 1;
            #pragma unroll
            for (int w = 0; w < 4; w++) {
                const int cm = 8 >> w;
                const int tm = 8 >> ((w + r) & 3);
                #pragma unroll
                for (int i0 = 0; i0 < 16; i0++) {
                    if ((i0 & cm) && !(i0 & tm)) {
                        int i1 = i0 | tm;
                        float tr = re[i0]; re[i0] = re[i1]; re[i1] = tr;
                        float ti = im[i0]; im[i0] = im[i1]; im[i1] = ti;
                    }
                }
            }
        }

        float o = bo[0];
        #pragma unroll
        for (int w = 0; w < 4; w++) {
            const int m = 8 >> w;
            float ev = 0.f;
            #pragma unroll
            for (int i = 0; i < 16; i++) {
                float p = re[i] * re[i] + im[i] * im[i];
                ev += (i & m) ? -p : p;
            }
            o = fmaf(Wo[w], ev, o);
        }
        out[bbase + tid] = o;
    }
}

extern "C" void kernel_launch(void* const* d_in, const int* in_sizes, int n_in,
                              void* d_out, int out_size) {
    const float* x    = (const float*)d_in[0];
    const float* W_ih = (const float*)d_in[1];
    const float* W_hh = (const float*)d_in[2];
    const float* b_ih = (const float*)d_in[3];
    const float* b_hh = (const float*)d_in[4];
    const float* Wp   = (const float*)d_in[5];
    const float* bp   = (const float*)d_in[6];
    const float* qw   = (const float*)d_in[7];
    const float* Wo   = (const float*)d_in[8];
    const float* bo   = (const float*)d_in[9];
    float* out = (float*)d_out;

    const size_t smem = SMEM_FLOATS * sizeof(float);
    cudaFuncSetAttribute(lstm_q_kernel, cudaFuncAttributeMaxDynamicSharedMemorySize, (int)smem);

    lstm_q_kernel<<<4096 / SAMPLES, NTHREADS, smem>>>(
        x, W_ih, W_hh, b_ih, b_hh, Wp, bp, qw, Wo, bo, out);
}

// round 10
// speedup vs baseline: 1.5189x; 1.5189x over previous
#include <cuda_runtime.h>

#define NTHREADS 256
#define SAMPLES  32
#define HDIM     50
#define G4       256           // 64 units * 4 gates, cols 4j+g
#define TSTEPS   256
#define HROW     34            // floats per h row [k][s0..s31] + 2 pad
#define HBUF     (50*HROW)
#define XROW     34
#define XBUF     (32*XROW)

typedef unsigned long long ull;

__device__ __forceinline__ ull pack2(float lo, float hi) {
    ull r; asm("mov.b64 %0, {%1,%2};" : "=l"(r) : "f"(lo), "f"(hi)); return r;
}
__device__ __forceinline__ void unpack2(ull v, float& lo, float& hi) {
    asm("mov.b64 {%0,%1}, %2;" : "=f"(lo), "=f"(hi) : "l"(v));
}
__device__ __forceinline__ ull fma2(ull a, ull b, ull c) {
    ull d; asm("fma.rn.f32x2 %0, %1, %2, %3;" : "=l"(d) : "l"(a), "l"(b), "l"(c)); return d;
}
__device__ __forceinline__ float sigmoidf_(float x) {
    return __fdividef(1.f, 1.f + __expf(-x));
}
__device__ __forceinline__ float tanhf_(float x) {
    return fmaf(2.f, sigmoidf_(2.f * x), -1.f);
}
__device__ __forceinline__ void cohort_bar(int id) {
    asm volatile("bar.sync %0, %1;" :: "r"(id), "r"(128) : "memory");
}

// Dynamic shared layout (floats):
//  Ws  [51*256] : rows 0..49 = W_hh (col c=4j+g), row 50 = W_ih; zeros j>=50
//  bbv [256]    : b_ih + b_hh (col 4j+g)
//  hb  [2*50*34]: double-buffered hidden state, rows [k][s]
//  xs  [2*32*34]: double-buffered x tiles, rows [tt][s]
#define OFF_WS  0
#define OFF_BB  (51*G4)
#define OFF_HB  (OFF_BB + G4)
#define OFF_XS  (OFF_HB + 2*HBUF)
#define SMEM_FLOATS (OFF_XS + 2*XBUF)

__global__ void __launch_bounds__(NTHREADS, 1) lstm_q_kernel(
    const float* __restrict__ x,    const float* __restrict__ W_ih,
    const float* __restrict__ W_hh, const float* __restrict__ b_ih,
    const float* __restrict__ b_hh, const float* __restrict__ Wp,
    const float* __restrict__ bp,   const float* __restrict__ qw,
    const float* __restrict__ Wo,   const float* __restrict__ bo,
    float* __restrict__ out)
{
    extern __shared__ float sm[];
    float* Ws  = sm + OFF_WS;
    float* bbv = sm + OFF_BB;
    float* hb  = sm + OFF_HB;
    float* xs  = sm + OFF_XS;

    const int tid   = threadIdx.x;
    const int lane  = tid & 31;
    const int warp  = tid >> 5;
    const int coh   = warp >> 2;           // cohort 0: warps 0-3 / cohort 1: warps 4-7
    const int ctid  = tid & 127;           // thread id within cohort
    const int ug    = warp & 1;            // unit group (0..1)
    const int sg    = (warp >> 1) & 1;     // sample group within cohort (0..1)
    const int j     = 32 * ug + lane;      // this thread's hidden unit (0..63)
    const int sb    = 16 * coh + 8 * sg;   // first of 8 samples
    const int bbase = blockIdx.x * SAMPLES;
    const int bid   = coh + 1;             // named barrier id for this cohort

    // ---- stage weights into shared (whole block) ----
    for (int idx = tid; idx < 51 * G4; idx += NTHREADS) {
        int k = idx >> 8, c = idx & 255;
        int jj = c >> 2, g = c & 3;
        float v = 0.f;
        if (jj < HDIM) {
            if (k < HDIM)      v = W_hh[(g * HDIM + jj) * HDIM + k];
            else               v = W_ih[g * HDIM + jj];          // row 50
        }
        Ws[idx] = v;
    }
    for (int idx = tid; idx < G4; idx += NTHREADS) {
        int jj = idx >> 2, g = idx & 3;
        bbv[idx] = (jj < HDIM) ? (b_ih[g * HDIM + jj] + b_hh[g * HDIM + jj]) : 0.f;
    }
    for (int idx = tid; idx < 2 * HBUF; idx += NTHREADS) hb[idx] = 0.f;
    // prefill x tile 0 (buffer 0): coalesced read, transposed store
    for (int idx = tid; idx < 32 * 32; idx += NTHREADS) {
        int ss = idx >> 5, tt = idx & 31;
        xs[tt * XROW + ss] = x[(bbase + ss) * TSTEPS + tt];
    }
    __syncthreads();

    // persistent packed biases / W_ih for this thread's 4 gate columns
    float4 b4 = *(const float4*)(bbv + 4 * j);
    ull bbg[4] = { pack2(b4.x, b4.x), pack2(b4.y, b4.y),
                   pack2(b4.z, b4.z), pack2(b4.w, b4.w) };
    float4 xw4 = *(const float4*)(Ws + 50 * G4 + 4 * j);
    ull xwg[4] = { pack2(xw4.x, xw4.x), pack2(xw4.y, xw4.y),
                   pack2(xw4.z, xw4.z), pack2(xw4.w, xw4.w) };

    float c_st[8];
    #pragma unroll
    for (int i = 0; i < 8; i++) c_st[i] = 0.f;

    int buf = 0;

    for (int t = 0; t < TSTEPS; t++) {
        cohort_bar(bid);               // this cohort's prev-step h writes (+ x refill) visible

        // refill next x tile for THIS COHORT's 16 samples only
        if ((t & 31) == 0 && t + 32 < TSTEPS) {
            float* xd = xs + (((t >> 5) & 1) ^ 1) * XBUF;
            for (int idx = ctid; idx < 16 * 32; idx += 128) {
                int ss = 16 * coh + (idx >> 5), tt = idx & 31;
                xd[tt * XROW + ss] = x[(bbase + ss) * TSTEPS + t + 32 + tt];
            }
        }

        const float* hB   = hb + buf * HBUF;
        const float* xrow = xs + ((t >> 5) & 1) * XBUF + (t & 31) * XROW + sb;

        ull acc[4][4];                 // [gate][sample-pair]
        #pragma unroll
        for (int g = 0; g < 4; g++)
            #pragma unroll
            for (int p = 0; p < 4; p++) acc[g][p] = bbg[g];

        #pragma unroll 10
        for (int k = 0; k < 50; k++) {
            float4 w4 = *(const float4*)(Ws + k * G4 + 4 * j);   // dense LDS.128
            ull wg[4] = { pack2(w4.x, w4.x), pack2(w4.y, w4.y),
                          pack2(w4.z, w4.z), pack2(w4.w, w4.w) };
            const float* hr = hB + k * HROW + sb;
            ull hp[4];
            #pragma unroll
            for (int p = 0; p < 4; p++) hp[p] = *(const ull*)(hr + 2 * p); // bcast LDS.64
            #pragma unroll
            for (int g = 0; g < 4; g++)
                #pragma unroll
                for (int p = 0; p < 4; p++)
                    acc[g][p] = fma2(hp[p], wg[g], acc[g][p]);
        }
        // x contribution (row 50 weights persistent in registers)
        {
            ull xp[4];
            #pragma unroll
            for (int p = 0; p < 4; p++) xp[p] = *(const ull*)(xrow + 2 * p);
            #pragma unroll
            for (int g = 0; g < 4; g++)
                #pragma unroll
                for (int p = 0; p < 4; p++)
                    acc[g][p] = fma2(xp[p], xwg[g], acc[g][p]);
        }

        // ---- gates: this thread = unit j, samples sb..sb+7 ----
        float* hn = hb + (buf ^ 1) * HBUF + j * HROW + sb;
        #pragma unroll
        for (int p = 0; p < 4; p++) {
            float zi0, zi1, zf0, zf1, zg0, zg1, zo0, zo1;
            unpack2(acc[0][p], zi0, zi1);
            unpack2(acc[1][p], zf0, zf1);
            unpack2(acc[2][p], zg0, zg1);
            unpack2(acc[3][p], zo0, zo1);
            float i0 = sigmoidf_(zi0), i1 = sigmoidf_(zi1);
            float f0 = sigmoidf_(zf0), f1 = sigmoidf_(zf1);
            float g0 = tanhf_(zg0),    g1 = tanhf_(zg1);
            float o0 = sigmoidf_(zo0), o1 = sigmoidf_(zo1);
            float c0 = fmaf(f0, c_st[2*p],   i0 * g0);
            float c1 = fmaf(f1, c_st[2*p+1], i1 * g1);
            c_st[2*p]   = c0;
            c_st[2*p+1] = c1;
            float h0 = o0 * tanhf_(c0);
            float h1 = o1 * tanhf_(c1);
            if (j < HDIM) *(ull*)(hn + 2 * p) = pack2(h0, h1);
        }
        buf ^= 1;
    }

    __syncthreads();   // both cohorts' final h visible

    // ---------------- quantum head: 1 thread per sample ----------------
    if (tid < SAMPLES) {
        const float* hfin = hb + buf * HBUF + tid;   // h[k][tid] at stride HROW

        float ang[4];
        #pragma unroll
        for (int w = 0; w < 4; w++) {
            float a = bp[w];
            for (int k = 0; k < HDIM; k++) a = fmaf(Wp[w * HDIM + k], hfin[k * HROW], a);
            ang[w] = tanhf_(a) * 1.5707963267948966f;
        }

        float re[16], im[16];
        #pragma unroll
        for (int i = 0; i < 16; i++) { re[i] = 0.f; im[i] = 0.f; }
        re[0] = 1.f;

        // RX embedding (wire w <-> bit 3-w)
        #pragma unroll
        for (int w = 0; w < 4; w++) {
            float sw, cw;
            sincosf(0.5f * ang[w], &sw, &cw);
            const int m = 8 >> w;
            #pragma unroll
            for (int i0 = 0; i0 < 16; i0++) {
                if (!(i0 & m)) {
                    int i1 = i0 | m;
                    float r0 = re[i0], q0 = im[i0], r1 = re[i1], q1 = im[i1];
                    re[i0] = cw * r0 + sw * q1;  im[i0] = cw * q0 - sw * r1;
                    re[i1] = cw * r1 + sw * q0;  im[i1] = cw * q1 - sw * r0;
                }
            }
        }

        // StronglyEntanglingLayers
        #pragma unroll
        for (int l = 0; l < 2; l++) {
            #pragma unroll
            for (int w = 0; w < 4; w++) {
                const float* q = qw + (l * 4 + w) * 3;
                float phi = q[0], th = q[1], om = q[2];
                float st_, ct_; sincosf(0.5f * th, &st_, &ct_);
                float sa, ca;   sincosf(0.5f * (phi + om), &sa, &ca);
                float sb2, cb2; sincosf(0.5f * (phi - om), &sb2, &cb2);
                float u00r =  ct_ * ca,  u00i = -ct_ * sa;
                float u01r = -st_ * cb2, u01i = -st_ * sb2;
                float u10r =  st_ * cb2, u10i = -st_ * sb2;
                float u11r =  ct_ * ca,  u11i =  ct_ * sa;
                const int m = 8 >> w;
                #pragma unroll
                for (int i0 = 0; i0 < 16; i0++) {
                    if (!(i0 & m)) {
                        int i1 = i0 | m;
                        float r0 = re[i0], q0 = im[i0], r1 = re[i1], q1 = im[i1];
                        re[i0] = u00r*r0 - u00i*q0 + u01r*r1 - u01i*q1;
                        im[i0] = u00r*q0 + u00i*r0 + u01r*q1 + u01i*r1;
                        re[i1] = u10r*r0 - u10i*q0 + u11r*r1 - u11i*q1;
                        im[i1] = u10r*q0 + u10i*r0 + u11r*q1 + u11i*r1;
                    }
                }
            }
            const int r = (l % 3) + 1;
            #pragma unroll
            for (int w = 0; w < 4; w++) {
                const int cm = 8 >> w;
                const int tm = 8 >> ((w + r) & 3);
                #pragma unroll
                for (int i0 = 0; i0 < 16; i0++) {
                    if ((i0 & cm) && !(i0 & tm)) {
                        int i1 = i0 | tm;
                        float tr = re[i0]; re[i0] = re[i1]; re[i1] = tr;
                        float ti = im[i0]; im[i0] = im[i1]; im[i1] = ti;
                    }
                }
            }
        }

        float o = bo[0];
        #pragma unroll
        for (int w = 0; w < 4; w++) {
            const int m = 8 >> w;
            float ev = 0.f;
            #pragma unroll
            for (int i = 0; i < 16; i++) {
                float p = re[i] * re[i] + im[i] * im[i];
                ev += (i & m) ? -p : p;
            }
            o = fmaf(Wo[w], ev, o);
        }
        out[bbase + tid] = o;
    }
}

extern "C" void kernel_launch(void* const* d_in, const int* in_sizes, int n_in,
                              void* d_out, int out_size) {
    const float* x    = (const float*)d_in[0];
    const float* W_ih = (const float*)d_in[1];
    const float* W_hh = (const float*)d_in[2];
    const float* b_ih = (const float*)d_in[3];
    const float* b_hh = (const float*)d_in[4];
    const float* Wp   = (const float*)d_in[5];
    const float* bp   = (const float*)d_in[6];
    const float* qw   = (const float*)d_in[7];
    const float* Wo   = (const float*)d_in[8];
    const float* bo   = (const float*)d_in[9];
    float* out = (float*)d_out;

    const size_t smem = SMEM_FLOATS * sizeof(float);
    cudaFuncSetAttribute(lstm_q_kernel, cudaFuncAttributeMaxDynamicSharedMemorySize, (int)smem);

    lstm_q_kernel<<<4096 / SAMPLES, NTHREADS, smem>>>(
        x, W_ih, W_hh, b_ih, b_hh, Wp, bp, qw, Wo, bo, out);
}